// round 16
// baseline (speedup 1.0000x reference)
#include <cuda_runtime.h>
#include <cuda_fp16.h>

// Problem constants
#define NB   2
#define NS   2048
#define ND   128
#define NH   32
#define NKVH 8
#define NHD  128
#define NW   4096
#define NMB  4

#define ATTN_SCALE 0.08838834764831845f            // 128^-0.5
#define KQSCALE (ATTN_SCALE * 1.4426950408889634f) // fold log2(e) into Q

// Scratch (allowed: __device__ globals)
__device__ __half g_qh[(size_t)NB * NH * NS * NHD];     // (b,h,s,d), pre-scaled by KQSCALE
__device__ __half g_kh[(size_t)NB * NKVH * NS * NHD];   // (b,kvh,s,d)
__device__ __half g_vh[(size_t)NB * NKVH * NS * NHD];
__device__ __half g_attnh[(size_t)NB * NS * NH * NHD];  // (b,s,h*d)
__device__ __half g_woh[(size_t)4096 * 128];
__device__ float  g_opart[(size_t)8 * 4096 * 128];      // split-K partials (8-way)
__device__ int    g_sync[128];                          // per-m-tile arrival counters

// ---------------------------------------------------------------------------
// helpers
// ---------------------------------------------------------------------------
__device__ __forceinline__ void cpasync16(void* smem_dst, const void* gsrc) {
    unsigned s = (unsigned)__cvta_generic_to_shared(smem_dst);
    asm volatile("cp.async.cg.shared.global [%0], [%1], 16;" :: "r"(s), "l"(gsrc));
}

__device__ __forceinline__ void mma16(float c[4], const unsigned a[4],
                                      unsigned b0, unsigned b1) {
    asm volatile(
        "mma.sync.aligned.m16n8k16.row.col.f32.f16.f16.f32 "
        "{%0,%1,%2,%3}, {%4,%5,%6,%7}, {%8,%9}, {%0,%1,%2,%3};"
        : "+f"(c[0]), "+f"(c[1]), "+f"(c[2]), "+f"(c[3])
        : "r"(a[0]), "r"(a[1]), "r"(a[2]), "r"(a[3]), "r"(b0), "r"(b1));
}

__device__ __forceinline__ void ldsm4(unsigned r[4], const void* p) {
    unsigned a = (unsigned)__cvta_generic_to_shared(p);
    asm volatile("ldmatrix.sync.aligned.m8n8.x4.shared.b16 {%0,%1,%2,%3}, [%4];"
                 : "=r"(r[0]), "=r"(r[1]), "=r"(r[2]), "=r"(r[3]) : "r"(a));
}

__device__ __forceinline__ void ldsm4t(unsigned r[4], const void* p) {
    unsigned a = (unsigned)__cvta_generic_to_shared(p);
    asm volatile("ldmatrix.sync.aligned.m8n8.x4.trans.shared.b16 {%0,%1,%2,%3}, [%4];"
                 : "=r"(r[0]), "=r"(r[1]), "=r"(r[2]), "=r"(r[3]) : "r"(a));
}

// pack two f32 -> f16x2, then ex2 on both halves
__device__ __forceinline__ unsigned ex2pack(float x, float y) {
    __half2 h = __floats2half2_rn(x, y);
    unsigned u = *reinterpret_cast<unsigned*>(&h);
    unsigned r;
    asm("ex2.approx.f16x2 %0, %1;" : "=r"(r) : "r"(u));
    return r;
}

#define ONES_H2 0x3C003C00u   // half2(1.0, 1.0)

// swizzled half-index for a row of 128 halves (16-byte chunk ^ row&7)
#define SWZ128(row, col) ((row) * 128 + (((((col) >> 3) ^ ((row) & 7))) << 3) + ((col) & 7))
// swizzled half-index for a row of 64 halves
#define SWZ64(row, col)  ((row) * 64  + (((((col) >> 3) ^ ((row) & 7))) << 3) + ((col) & 7))

// ---------------------------------------------------------------------------
// Fused prep kernel, 64KB smem (2 CTAs/SM). Block roles:
//   [0, 512):      K/V projection, 3xFP16 split, k-split into 2 passes of 64.
//   [512, 1536):   Q projection (plain fp16), rotary + KQSCALE.
//   [1536, 1792):  wo fp32 -> fp16 convert (+ zero g_sync counters).
// ---------------------------------------------------------------------------
#define PREP_PROJ_BLOCKS  512
#define PREP_QPROJ_BLOCKS 1024
#define PREP_CONV_BLOCKS  256
#define PREP_BLOCKS (PREP_PROJ_BLOCKS + PREP_QPROJ_BLOCKS + PREP_CONV_BLOCKS)
#define PREP_SMEM_BYTES 65536

__global__ void __launch_bounds__(256) prep_kernel(
    const float* __restrict__ x, const float* __restrict__ wq,
    const float* __restrict__ wk, const float* __restrict__ wv,
    const float* __restrict__ freqs, const float* __restrict__ wo,
    float* __restrict__ cache_k)
{
    const int bid = blockIdx.x;
    const int tid = threadIdx.x;

    const int lane = tid & 31;
    const int w8   = tid >> 5;
    const int wm   = w8 >> 1;
    const int wn   = w8 & 1;
    const int g    = lane >> 2;
    const int t4   = lane & 3;
    const int q4   = lane >> 3;

    extern __shared__ __half psm[];

    if (bid < PREP_PROJ_BLOCKS) {
        // ---- K/V projection role (3xFP16 split, 2-pass k-split) ----
        __half* sxh = psm;               // 128 x 64
        __half* sxl = psm + 8192;        // 128 x 64
        __half* swh = psm + 16384;       // 64 x 128
        __half* swl = psm + 24576;       // 64 x 128

        const int rb = bid >> 4;
        const int cb = bid & 15;
        const int kvsel = cb >> 3;
        const int n0 = (cb & 7) * 128;
        const float* wmat = kvsel ? wv : wk;
        const int m0 = rb * 128;

        float C[2][8][4] = {};

        #pragma unroll
        for (int kc = 0; kc < 2; kc++) {
            if (kc) __syncthreads();     // protect smem reuse

            #pragma unroll
            for (int i = 0; i < 8; i++) {
                int idx = tid + i * 256;
                int row = idx >> 4;
                int c4  = (idx & 15) * 4;
                float4 v = *reinterpret_cast<const float4*>(
                    &x[(size_t)(m0 + row) * 128 + kc * 64 + c4]);
                __half2 h0 = __floats2half2_rn(v.x, v.y);
                __half2 h1 = __floats2half2_rn(v.z, v.w);
                __half2 l0 = __floats2half2_rn(v.x - __half2float(__low2half(h0)),
                                               v.y - __half2float(__high2half(h0)));
                __half2 l1 = __floats2half2_rn(v.z - __half2float(__low2half(h1)),
                                               v.w - __half2float(__high2half(h1)));
                *reinterpret_cast<__half2*>(&sxh[SWZ64(row, c4)])     = h0;
                *reinterpret_cast<__half2*>(&sxh[SWZ64(row, c4) + 2]) = h1;
                *reinterpret_cast<__half2*>(&sxl[SWZ64(row, c4)])     = l0;
                *reinterpret_cast<__half2*>(&sxl[SWZ64(row, c4) + 2]) = l1;
            }
            #pragma unroll
            for (int i = 0; i < 8; i++) {
                int idx = tid + i * 256;
                int row = idx >> 5;
                int c4  = (idx & 31) * 4;
                float4 wv4 = *reinterpret_cast<const float4*>(
                    &wmat[(size_t)(kc * 64 + row) * 1024 + n0 + c4]);
                __half2 wh0 = __floats2half2_rn(wv4.x, wv4.y);
                __half2 wh1 = __floats2half2_rn(wv4.z, wv4.w);
                __half2 wl0 = __floats2half2_rn(wv4.x - __half2float(__low2half(wh0)),
                                                wv4.y - __half2float(__high2half(wh0)));
                __half2 wl1 = __floats2half2_rn(wv4.z - __half2float(__low2half(wh1)),
                                                wv4.w - __half2float(__high2half(wh1)));
                *reinterpret_cast<__half2*>(&swh[SWZ128(row, c4)])     = wh0;
                *reinterpret_cast<__half2*>(&swh[SWZ128(row, c4) + 2]) = wh1;
                *reinterpret_cast<__half2*>(&swl[SWZ128(row, c4)])     = wl0;
                *reinterpret_cast<__half2*>(&swl[SWZ128(row, c4) + 2]) = wl1;
            }
            __syncthreads();

            #pragma unroll
            for (int ks = 0; ks < 4; ks++) {
                unsigned ah[2][4], al[2][4];
                #pragma unroll
                for (int mt = 0; mt < 2; mt++) {
                    int row = wm * 32 + mt * 16 + ((q4 & 1) << 3) + (lane & 7);
                    int ch  = 2 * ks + (q4 >> 1);
                    int so  = row * 64 + ((ch ^ (row & 7)) << 3);
                    ldsm4(ah[mt], &sxh[so]);
                    ldsm4(al[mt], &sxl[so]);
                }
                #pragma unroll
                for (int np = 0; np < 4; np++) {
                    unsigned bh[4], bl[4];
                    int row = ks * 16 + ((q4 & 1) << 3) + (lane & 7);
                    int ch  = wn * 8 + np * 2 + (q4 >> 1);
                    int so  = row * 128 + ((ch ^ (row & 7)) << 3);
                    ldsm4t(bh, &swh[so]);
                    ldsm4t(bl, &swl[so]);
                    #pragma unroll
                    for (int mt = 0; mt < 2; mt++) {
                        mma16(C[mt][2 * np],     ah[mt], bh[0], bh[1]);
                        mma16(C[mt][2 * np + 1], ah[mt], bh[2], bh[3]);
                        mma16(C[mt][2 * np],     al[mt], bh[0], bh[1]);
                        mma16(C[mt][2 * np + 1], al[mt], bh[2], bh[3]);
                        mma16(C[mt][2 * np],     ah[mt], bl[0], bl[1]);
                        mma16(C[mt][2 * np + 1], ah[mt], bl[2], bl[3]);
                    }
                }
            }
        }

        __half* dst = kvsel ? g_vh : g_kh;
        float* cache = cache_k + (size_t)kvsel * NMB * NW * NKVH * NHD;

        #pragma unroll
        for (int mt = 0; mt < 2; mt++) {
            #pragma unroll
            for (int rr = 0; rr < 2; rr++) {
                int row = m0 + wm * 32 + mt * 16 + rr * 8 + g;
                int b = row >> 11;
                int s = row & 2047;
                #pragma unroll
                for (int ns = 0; ns < 8; ns++) {
                    int coll = n0 + wn * 64 + ns * 8 + 2 * t4;
                    int head = coll >> 7;
                    int hd = coll & 127;
                    float v0 = C[mt][ns][2 * rr];
                    float v1 = C[mt][ns][2 * rr + 1];
                    if (!kvsel) {
                        float2 cs = *reinterpret_cast<const float2*>(
                            &freqs[(s * 64 + (hd >> 1)) * 2]);
                        float r0v = v0 * cs.x - v1 * cs.y;
                        float r1v = v0 * cs.y + v1 * cs.x;
                        v0 = r0v; v1 = r1v;
                    }
                    __half2 hv = __floats2half2_rn(v0, v1);
                    float2 cf = __half22float2(hv);
                    *reinterpret_cast<float2*>(
                        &cache[(((size_t)b * NW + s) * NKVH + head) * NHD + hd]) = cf;
                    *reinterpret_cast<__half2*>(
                        &dst[(((size_t)b * NKVH + head) * NS + s) * NHD + hd]) = hv;
                }
            }
        }
        return;
    }

    if (bid < PREP_PROJ_BLOCKS + PREP_QPROJ_BLOCKS) {
        // ---- Q projection role (plain fp16) ----
        int rb = bid - PREP_PROJ_BLOCKS;
        __half* sx = psm;
        __half* sw = psm + 16384;

        const int m0 = (rb >> 5) * 128;
        const int n0 = (rb & 31) * 128;

        #pragma unroll
        for (int i = 0; i < 16; i++) {
            int idx = tid + i * 256;
            int row = idx >> 5;
            int c4  = (idx & 31) * 4;
            float4 v = *reinterpret_cast<const float4*>(&x[(size_t)(m0 + row) * 128 + c4]);
            *reinterpret_cast<__half2*>(&sx[SWZ128(row, c4)])     = __floats2half2_rn(v.x, v.y);
            *reinterpret_cast<__half2*>(&sx[SWZ128(row, c4) + 2]) = __floats2half2_rn(v.z, v.w);

            float4 wv4 = *reinterpret_cast<const float4*>(&wq[(size_t)row * 4096 + n0 + c4]);
            *reinterpret_cast<__half2*>(&sw[SWZ128(row, c4)])     = __floats2half2_rn(wv4.x, wv4.y);
            *reinterpret_cast<__half2*>(&sw[SWZ128(row, c4) + 2]) = __floats2half2_rn(wv4.z, wv4.w);
        }
        __syncthreads();

        float C[2][8][4] = {};

        #pragma unroll
        for (int ks = 0; ks < 8; ks++) {
            unsigned a[2][4];
            #pragma unroll
            for (int mt = 0; mt < 2; mt++) {
                int row = wm * 32 + mt * 16 + ((q4 & 1) << 3) + (lane & 7);
                int ch  = 2 * ks + (q4 >> 1);
                ldsm4(a[mt], &sx[row * 128 + ((ch ^ (row & 7)) << 3)]);
            }
            #pragma unroll
            for (int np = 0; np < 4; np++) {
                unsigned bb[4];
                int row = ks * 16 + ((q4 & 1) << 3) + (lane & 7);
                int ch  = wn * 8 + np * 2 + (q4 >> 1);
                ldsm4t(bb, &sw[row * 128 + ((ch ^ (row & 7)) << 3)]);
                mma16(C[0][2 * np],     a[0], bb[0], bb[1]);
                mma16(C[0][2 * np + 1], a[0], bb[2], bb[3]);
                mma16(C[1][2 * np],     a[1], bb[0], bb[1]);
                mma16(C[1][2 * np + 1], a[1], bb[2], bb[3]);
            }
        }

        #pragma unroll
        for (int mt = 0; mt < 2; mt++) {
            #pragma unroll
            for (int rr = 0; rr < 2; rr++) {
                int row = m0 + wm * 32 + mt * 16 + rr * 8 + g;
                int b = row >> 11;
                int s = row & 2047;
                #pragma unroll
                for (int ns = 0; ns < 8; ns++) {
                    int col = n0 + wn * 64 + ns * 8 + 2 * t4;
                    int head = col >> 7;
                    int hd = col & 127;
                    float2 cs = *reinterpret_cast<const float2*>(
                        &freqs[(s * 64 + (hd >> 1)) * 2]);
                    float v0 = C[mt][ns][2 * rr];
                    float v1 = C[mt][ns][2 * rr + 1];
                    float r0v = (v0 * cs.x - v1 * cs.y) * KQSCALE;
                    float r1v = (v0 * cs.y + v1 * cs.x) * KQSCALE;
                    *reinterpret_cast<__half2*>(
                        &g_qh[(((size_t)b * NH + head) * NS + s) * NHD + hd]) =
                        __floats2half2_rn(r0v, r1v);
                }
            }
        }
        return;
    }

    // ---- convert role (+ counter reset) ----
    int rc = bid - PREP_PROJ_BLOCKS - PREP_QPROJ_BLOCKS;
    if (rc == 0 && tid < 128) g_sync[tid] = 0;
    #pragma unroll
    for (int t = 0; t < 4; t++) {
        int i = rc * 256 + tid + t * 65536;
        float2 v = reinterpret_cast<const float2*>(wo)[i];
        reinterpret_cast<__half2*>(g_woh)[i] = __floats2half2_rn(v.x, v.y);
    }
}

// ---------------------------------------------------------------------------
// FA2-style fp16 flash attention, 2 CTAs/SM, stateless softmax, 1 barrier/tile.
// ---------------------------------------------------------------------------
#define QT 128
#define KT 64
#define SQ_H (QT * 128)
#define SK_H (KT * 128)
#define ATTN_SMEM_BYTES ((SQ_H + 4 * SK_H) * 2)   // 98304

__global__ void __launch_bounds__(256, 2) attn_kernel() {
    extern __shared__ __half smh[];
    __half* sq  = smh;
    __half* skb = sq + SQ_H;
    __half* svb = skb + 2 * SK_H;

    const int qb = (int)gridDim.x - 1 - (int)blockIdx.x;
    const int h  = blockIdx.y;
    const int b  = blockIdx.z;
    const int kvh = h >> 2;
    const int tid  = threadIdx.x;
    const int lane = tid & 31;
    const int w    = tid >> 5;
    const int g    = lane >> 2;
    const int t4   = lane & 3;
    const int q4   = lane >> 3;

    const __half* qg = g_qh + (((size_t)b * NH + h) * NS + (size_t)qb * QT) * NHD;
    const __half* kg = g_kh + ((size_t)b * NKVH + kvh) * NS * NHD;
    const __half* vg = g_vh + ((size_t)b * NKVH + kvh) * NS * NHD;

    const int nkb = 2 * qb + 2;

    #pragma unroll
    for (int i = 0; i < 4; i++) {
        int idx = tid + i * 256;
        int row = idx >> 4, c = idx & 15;
        cpasync16(&skb[SWZ128(row, c * 8)], &kg[(size_t)row * 128 + c * 8]);
        cpasync16(&svb[SWZ128(row, c * 8)], &vg[(size_t)row * 128 + c * 8]);
    }
    asm volatile("cp.async.commit_group;");

    #pragma unroll
    for (int i = 0; i < 8; i++) {
        int idx = tid + i * 256;
        int row = idx >> 4, c = idx & 15;
        *reinterpret_cast<uint4*>(&sq[SWZ128(row, c * 8)]) =
            *reinterpret_cast<const uint4*>(&qg[(size_t)row * 128 + c * 8]);
    }

    float O[16][4] = {};
    float Lc[4] = {};

    for (int kb = 0; kb < nkb; kb++) {
        const int cur = kb & 1;

        asm volatile("cp.async.wait_group 0;");
        __syncthreads();

        if (kb + 1 < nkb) {
            __half* skn = skb + (cur ^ 1) * SK_H;
            __half* svn = svb + (cur ^ 1) * SK_H;
            const size_t off = (size_t)(kb + 1) * KT * 128;
            #pragma unroll
            for (int i = 0; i < 4; i++) {
                int idx = tid + i * 256;
                int row = idx >> 4, c = idx & 15;
                cpasync16(&skn[SWZ128(row, c * 8)], &kg[off + (size_t)row * 128 + c * 8]);
                cpasync16(&svn[SWZ128(row, c * 8)], &vg[off + (size_t)row * 128 + c * 8]);
            }
            asm volatile("cp.async.commit_group;");
        }

        const __half* skc = skb + cur * SK_H;
        const __half* svc = svb + cur * SK_H;

        const bool skip = (kb * KT > qb * QT + w * 16 + 15);
        if (!skip) {
            // ---- scores: C = Q . K^T, warp tile 16x64 ----
            float C[8][4] = {};
            #pragma unroll
            for (int ks = 0; ks < 8; ks++) {
                unsigned qa[4];
                {
                    int row = w * 16 + ((q4 & 1) << 3) + (lane & 7);
                    int ch  = 2 * ks + (q4 >> 1);
                    ldsm4(qa, &sq[row * 128 + ((ch ^ (row & 7)) << 3)]);
                }
                #pragma unroll
                for (int np = 0; np < 4; np++) {
                    unsigned bb[4];
                    int n  = np * 16 + ((q4 >> 1) << 3) + (lane & 7);
                    int ch = 2 * ks + (q4 & 1);
                    ldsm4(bb, &skc[n * 128 + ((ch ^ (n & 7)) << 3)]);
                    mma16(C[2 * np],     qa, bb[0], bb[1]);
                    mma16(C[2 * np + 1], qa, bb[2], bb[3]);
                }
            }

            // causal mask (log2 domain; -30 -> exp2 = 0 in fp16)
            if (kb * KT + KT - 1 > qb * QT + w * 16) {
                const int grow0 = qb * QT + w * 16 + g;
                #pragma unroll
                for (int ns = 0; ns < 8; ns++) {
                    int gc = kb * KT + ns * 8 + 2 * t4;
                    if (gc     > grow0)     C[ns][0] = -30.f;
                    if (gc + 1 > grow0)     C[ns][1] = -30.f;
                    if (gc     > grow0 + 8) C[ns][2] = -30.f;
                    if (gc + 1 > grow0 + 8) C[ns][3] = -30.f;
                }
            }

            // ---- stateless softmax: P = exp2(C), packed to fp16 A-frags ----
            unsigned pa[4][4];
            #pragma unroll
            for (int j = 0; j < 4; j++) {
                pa[j][0] = ex2pack(C[2 * j][0],     C[2 * j][1]);
                pa[j][1] = ex2pack(C[2 * j][2],     C[2 * j][3]);
                pa[j][2] = ex2pack(C[2 * j + 1][0], C[2 * j + 1][1]);
                pa[j][3] = ex2pack(C[2 * j + 1][2], C[2 * j + 1][3]);
            }

            // normalizer: Lc += P @ ones
            #pragma unroll
            for (int j = 0; j < 4; j++)
                mma16(Lc, pa[j], ONES_H2, ONES_H2);

            // ---- PV: O += P . V, warp tile 16x128 ----
            #pragma unroll
            for (int j = 0; j < 4; j++) {
                #pragma unroll
                for (int ng = 0; ng < 8; ng++) {
                    unsigned bb[4];
                    int row = j * 16 + ((q4 & 1) << 3) + (lane & 7);
                    int ch  = ng * 2 + (q4 >> 1);
                    ldsm4t(bb, &svc[row * 128 + ((ch ^ (row & 7)) << 3)]);
                    mma16(O[2 * ng],     pa[j], bb[0], bb[1]);
                    mma16(O[2 * ng + 1], pa[j], bb[2], bb[3]);
                }
            }
        }
    }

    {
        float inv0 = 1.f / Lc[0];
        float inv1 = 1.f / Lc[2];
        int s0r = qb * QT + w * 16 + g;
        int s1r = s0r + 8;
        size_t base0 = ((size_t)b * NS + s0r) * (NH * NHD) + (size_t)h * NHD;
        size_t base1 = ((size_t)b * NS + s1r) * (NH * NHD) + (size_t)h * NHD;
        #pragma unroll
        for (int ns = 0; ns < 16; ns++) {
            int col = ns * 8 + 2 * t4;
            *reinterpret_cast<__half2*>(&g_attnh[base0 + col]) =
                __floats2half2_rn(O[ns][0] * inv0, O[ns][1] * inv0);
            *reinterpret_cast<__half2*>(&g_attnh[base1 + col]) =
                __floats2half2_rn(O[ns][2] * inv1, O[ns][3] * inv1);
        }
    }
}

// ---------------------------------------------------------------------------
// Output projection, stage 1 (split-K 8-way, fused last-arrival reduce)
// + cache zero-fill role.
// ---------------------------------------------------------------------------
#define OSA_H (32 * 64)
#define OSW_H (64 * 128)
#define OPROJ_SMEM_BYTES ((2 * OSA_H + 2 * OSW_H) * 2)   // 40960
#define OPROJ_GEMM_BLOCKS 1024
#define OPROJ_ZERO_BLOCKS 768
#define OPROJ_BLOCKS (OPROJ_GEMM_BLOCKS + OPROJ_ZERO_BLOCKS)

__global__ void __launch_bounds__(256) oproj_split_kernel(
    float* __restrict__ cache_k, float* __restrict__ out)
{
    const int bid = blockIdx.x;
    const int tid = threadIdx.x;

    if (bid >= OPROJ_GEMM_BLOCKS) {
        int rb = bid - OPROJ_GEMM_BLOCKS;
        const size_t nz = 3145728, per = 4194304;
        float4 z = make_float4(0.f, 0.f, 0.f, 0.f);
        #pragma unroll 4
        for (int t = tid; t < 8192; t += 256) {
            size_t i = (size_t)rb * 8192 + t;
            size_t c = i / nz, j = i - c * nz;
            size_t off;
            if (j < 524288)        off = 524288 + j;
            else if (j < 1048576)  off = 1572864 + (j - 524288);
            else                   off = 2097152 + (j - 1048576);
            reinterpret_cast<float4*>(cache_k)[c * per + off] = z;
        }
        return;
    }

    extern __shared__ __half osm[];
    __half* sa = osm;
    __half* sw = osm + 2 * OSA_H;
    __shared__ int s_arrival;

    const int ks4 = bid >> 7;              // 0..7
    const int mb  = bid & 127;             // m-tile index
    const int m0  = mb * 32;
    const int kbase = ks4 * 512;
    const int lane = tid & 31;
    const int w    = tid >> 5;
    const int wm   = w >> 2;
    const int wn   = w & 3;
    const int g    = lane >> 2;
    const int t4   = lane & 3;
    const int q4   = lane >> 3;

    float C[4][4] = {};

    {
        int idx = tid;
        int row = idx >> 3, c = idx & 7;
        cpasync16(&sa[SWZ64(row, c * 8)],
                  &g_attnh[(size_t)(m0 + row) * 4096 + kbase + c * 8]);
    }
    #pragma unroll
    for (int i = 0; i < 4; i++) {
        int idx = tid + i * 256;
        int row = idx >> 4, c = idx & 15;
        cpasync16(&sw[SWZ128(row, c * 8)], &g_woh[(size_t)(kbase + row) * 128 + c * 8]);
    }
    asm volatile("cp.async.commit_group;");

    for (int kc = 0; kc < 8; kc++) {
        const int cur = kc & 1;
        if (kc + 1 < 8) {
            __half* san = sa + (cur ^ 1) * OSA_H;
            __half* swn = sw + (cur ^ 1) * OSW_H;
            const int k0 = kbase + (kc + 1) * 64;
            {
                int idx = tid;
                int row = idx >> 3, c = idx & 7;
                cpasync16(&san[SWZ64(row, c * 8)],
                          &g_attnh[(size_t)(m0 + row) * 4096 + k0 + c * 8]);
            }
            #pragma unroll
            for (int i = 0; i < 4; i++) {
                int idx = tid + i * 256;
                int row = idx >> 4, c = idx & 15;
                cpasync16(&swn[SWZ128(row, c * 8)],
                          &g_woh[(size_t)(k0 + row) * 128 + c * 8]);
            }
            asm volatile("cp.async.commit_group;");
            asm volatile("cp.async.wait_group 1;");
        } else {
            asm volatile("cp.async.wait_group 0;");
        }
        __syncthreads();

        const __half* sac = sa + cur * OSA_H;
        const __half* swc = sw + cur * OSW_H;

        #pragma unroll
        for (int ks = 0; ks < 4; ks++) {
            unsigned a[4];
            {
                int row = wm * 16 + ((q4 & 1) << 3) + (lane & 7);
                int ch  = 2 * ks + (q4 >> 1);
                ldsm4(a, &sac[row * 64 + ((ch ^ (row & 7)) << 3)]);
            }
            #pragma unroll
            for (int np = 0; np < 2; np++) {
                unsigned bb[4];
                int row = ks * 16 + ((q4 & 1) << 3) + (lane & 7);
                int ch  = wn * 4 + np * 2 + (q4 >> 1);
                ldsm4t(bb, &swc[row * 128 + ((ch ^ (row & 7)) << 3)]);
                mma16(C[2 * np],     a, bb[0], bb[1]);
                mma16(C[2 * np + 1], a, bb[2], bb[3]);
            }
        }
        __syncthreads();
    }

    // store partial
    {
        float* part = g_opart + (size_t)ks4 * 4096 * 128;
        int r0 = m0 + wm * 16 + g;
        #pragma unroll
        for (int ns = 0; ns < 4; ns++) {
            int col = wn * 32 + ns * 8 + 2 * t4;
            *reinterpret_cast<float2*>(&part[(size_t)r0 * 128 + col]) =
                make_float2(C[ns][0], C[ns][1]);
            *reinterpret_cast<float2*>(&part[(size_t)(r0 + 8) * 128 + col]) =
                make_float2(C[ns][2], C[ns][3]);
        }
    }

    // last-arrival reduction for this m-tile
    __threadfence();
    if (tid == 0) s_arrival = atomicAdd(&g_sync[mb], 1);
    __syncthreads();
    if (s_arrival == 7) {
        __threadfence();
        const float4* p = reinterpret_cast<const float4*>(g_opart);
        float4* o4 = reinterpret_cast<float4*>(out);
        const int base = m0 * 32;            // float4 index of row m0
        #pragma unroll
        for (int t = 0; t < 4; t++) {
            int i = base + tid + t * 256;    // 1024 float4 per m-tile
            float4 r = make_float4(0.f, 0.f, 0.f, 0.f);
            #pragma unroll
            for (int k = 0; k < 8; k++) {
                float4 a = p[i + (size_t)k * 131072];
                r.x += a.x; r.y += a.y; r.z += a.z; r.w += a.w;
            }
            o4[i] = r;
        }
    }
}

// ---------------------------------------------------------------------------
// Launch
// ---------------------------------------------------------------------------
extern "C" void kernel_launch(void* const* d_in, const int* in_sizes, int n_in,
                              void* d_out, int out_size) {
    const float* x     = (const float*)d_in[0];
    const float* wq    = (const float*)d_in[1];
    const float* wk    = (const float*)d_in[2];
    const float* wv    = (const float*)d_in[3];
    const float* wo    = (const float*)d_in[4];
    const float* freqs = (const float*)d_in[5];

    float* out = (float*)d_out;
    float* cache_k_out = out + (size_t)NB * NS * ND;

    (void)in_sizes; (void)n_in; (void)out_size;

    static int attrs_set = 0;
    if (!attrs_set) {
        cudaFuncSetAttribute(attn_kernel, cudaFuncAttributeMaxDynamicSharedMemorySize,
                             ATTN_SMEM_BYTES);
        cudaFuncSetAttribute(oproj_split_kernel, cudaFuncAttributeMaxDynamicSharedMemorySize,
                             OPROJ_SMEM_BYTES);
        cudaFuncSetAttribute(prep_kernel, cudaFuncAttributeMaxDynamicSharedMemorySize,
                             PREP_SMEM_BYTES);
        attrs_set = 1;
    }

    prep_kernel<<<PREP_BLOCKS, 256, PREP_SMEM_BYTES>>>(x, wq, wk, wv, freqs, wo,
                                                       cache_k_out);

    attn_kernel<<<dim3(NS / QT, NH, NB), 256, ATTN_SMEM_BYTES>>>();

    oproj_split_kernel<<<OPROJ_BLOCKS, 256, OPROJ_SMEM_BYTES>>>(cache_k_out, out);
}

// round 17
// speedup vs baseline: 1.0275x; 1.0275x over previous
#include <cuda_runtime.h>
#include <cuda_fp16.h>

// Problem constants
#define NB   2
#define NS   2048
#define ND   128
#define NH   32
#define NKVH 8
#define NHD  128
#define NW   4096
#define NMB  4

#define ATTN_SCALE 0.08838834764831845f            // 128^-0.5
#define KQSCALE (ATTN_SCALE * 1.4426950408889634f) // fold log2(e) into Q

// Scratch (allowed: __device__ globals)
__device__ __half g_qh[(size_t)NB * NH * NS * NHD];     // (b,h,s,d), pre-scaled by KQSCALE
__device__ __half g_kh[(size_t)NB * NKVH * NS * NHD];   // (b,kvh,s,d)
__device__ __half g_vh[(size_t)NB * NKVH * NS * NHD];
__device__ __half g_attnh[(size_t)NB * NS * NH * NHD];  // (b,s,h*d)
__device__ __half g_woh[(size_t)4096 * 128];
__device__ float  g_opart[(size_t)8 * 4096 * 128];      // split-K partials (8-way)

// ---------------------------------------------------------------------------
// helpers
// ---------------------------------------------------------------------------
__device__ __forceinline__ void cpasync16(void* smem_dst, const void* gsrc) {
    unsigned s = (unsigned)__cvta_generic_to_shared(smem_dst);
    asm volatile("cp.async.cg.shared.global [%0], [%1], 16;" :: "r"(s), "l"(gsrc));
}

__device__ __forceinline__ void mma16(float c[4], const unsigned a[4],
                                      unsigned b0, unsigned b1) {
    asm volatile(
        "mma.sync.aligned.m16n8k16.row.col.f32.f16.f16.f32 "
        "{%0,%1,%2,%3}, {%4,%5,%6,%7}, {%8,%9}, {%0,%1,%2,%3};"
        : "+f"(c[0]), "+f"(c[1]), "+f"(c[2]), "+f"(c[3])
        : "r"(a[0]), "r"(a[1]), "r"(a[2]), "r"(a[3]), "r"(b0), "r"(b1));
}

__device__ __forceinline__ void ldsm4(unsigned r[4], const void* p) {
    unsigned a = (unsigned)__cvta_generic_to_shared(p);
    asm volatile("ldmatrix.sync.aligned.m8n8.x4.shared.b16 {%0,%1,%2,%3}, [%4];"
                 : "=r"(r[0]), "=r"(r[1]), "=r"(r[2]), "=r"(r[3]) : "r"(a));
}

__device__ __forceinline__ void ldsm4t(unsigned r[4], const void* p) {
    unsigned a = (unsigned)__cvta_generic_to_shared(p);
    asm volatile("ldmatrix.sync.aligned.m8n8.x4.trans.shared.b16 {%0,%1,%2,%3}, [%4];"
                 : "=r"(r[0]), "=r"(r[1]), "=r"(r[2]), "=r"(r[3]) : "r"(a));
}

// pack two f32 -> f16x2, then ex2 on both halves
__device__ __forceinline__ unsigned ex2pack(float x, float y) {
    __half2 h = __floats2half2_rn(x, y);
    unsigned u = *reinterpret_cast<unsigned*>(&h);
    unsigned r;
    asm("ex2.approx.f16x2 %0, %1;" : "=r"(r) : "r"(u));
    return r;
}

#define ONES_H2 0x3C003C00u   // half2(1.0, 1.0)

// swizzled half-index for a row of 128 halves (16-byte chunk ^ row&7)
#define SWZ128(row, col) ((row) * 128 + (((((col) >> 3) ^ ((row) & 7))) << 3) + ((col) & 7))
// swizzled half-index for a row of 64 halves
#define SWZ64(row, col)  ((row) * 64  + (((((col) >> 3) ^ ((row) & 7))) << 3) + ((col) & 7))

// ---------------------------------------------------------------------------
// Fused prep kernel, 64KB smem, capped at 128 regs -> 2 CTAs/SM. Block roles:
//   [0, 512):      K/V projection, 3xFP16 split, k-split into 2 passes of 64.
//   [512, 1536):   Q projection (plain fp16), rotary + KQSCALE.
//   [1536, 1792):  wo fp32 -> fp16 convert.
// ---------------------------------------------------------------------------
#define PREP_PROJ_BLOCKS  512
#define PREP_QPROJ_BLOCKS 1024
#define PREP_CONV_BLOCKS  256
#define PREP_BLOCKS (PREP_PROJ_BLOCKS + PREP_QPROJ_BLOCKS + PREP_CONV_BLOCKS)
#define PREP_SMEM_BYTES 65536

__global__ void __launch_bounds__(256, 2) prep_kernel(
    const float* __restrict__ x, const float* __restrict__ wq,
    const float* __restrict__ wk, const float* __restrict__ wv,
    const float* __restrict__ freqs, const float* __restrict__ wo,
    float* __restrict__ cache_k)
{
    const int bid = blockIdx.x;
    const int tid = threadIdx.x;

    const int lane = tid & 31;
    const int w8   = tid >> 5;
    const int wm   = w8 >> 1;
    const int wn   = w8 & 1;
    const int g    = lane >> 2;
    const int t4   = lane & 3;
    const int q4   = lane >> 3;

    extern __shared__ __half psm[];

    if (bid < PREP_PROJ_BLOCKS) {
        // ---- K/V projection role (3xFP16 split, 2-pass k-split) ----
        __half* sxh = psm;               // 128 x 64
        __half* sxl = psm + 8192;        // 128 x 64
        __half* swh = psm + 16384;       // 64 x 128
        __half* swl = psm + 24576;       // 64 x 128

        const int rb = bid >> 4;
        const int cb = bid & 15;
        const int kvsel = cb >> 3;
        const int n0 = (cb & 7) * 128;
        const float* wmat = kvsel ? wv : wk;
        const int m0 = rb * 128;

        float C[2][8][4] = {};

        #pragma unroll
        for (int kc = 0; kc < 2; kc++) {
            if (kc) __syncthreads();     // protect smem reuse

            #pragma unroll
            for (int i = 0; i < 8; i++) {
                int idx = tid + i * 256;
                int row = idx >> 4;
                int c4  = (idx & 15) * 4;
                float4 v = *reinterpret_cast<const float4*>(
                    &x[(size_t)(m0 + row) * 128 + kc * 64 + c4]);
                __half2 h0 = __floats2half2_rn(v.x, v.y);
                __half2 h1 = __floats2half2_rn(v.z, v.w);
                __half2 l0 = __floats2half2_rn(v.x - __half2float(__low2half(h0)),
                                               v.y - __half2float(__high2half(h0)));
                __half2 l1 = __floats2half2_rn(v.z - __half2float(__low2half(h1)),
                                               v.w - __half2float(__high2half(h1)));
                *reinterpret_cast<__half2*>(&sxh[SWZ64(row, c4)])     = h0;
                *reinterpret_cast<__half2*>(&sxh[SWZ64(row, c4) + 2]) = h1;
                *reinterpret_cast<__half2*>(&sxl[SWZ64(row, c4)])     = l0;
                *reinterpret_cast<__half2*>(&sxl[SWZ64(row, c4) + 2]) = l1;
            }
            #pragma unroll
            for (int i = 0; i < 8; i++) {
                int idx = tid + i * 256;
                int row = idx >> 5;
                int c4  = (idx & 31) * 4;
                float4 wv4 = *reinterpret_cast<const float4*>(
                    &wmat[(size_t)(kc * 64 + row) * 1024 + n0 + c4]);
                __half2 wh0 = __floats2half2_rn(wv4.x, wv4.y);
                __half2 wh1 = __floats2half2_rn(wv4.z, wv4.w);
                __half2 wl0 = __floats2half2_rn(wv4.x - __half2float(__low2half(wh0)),
                                                wv4.y - __half2float(__high2half(wh0)));
                __half2 wl1 = __floats2half2_rn(wv4.z - __half2float(__low2half(wh1)),
                                                wv4.w - __half2float(__high2half(wh1)));
                *reinterpret_cast<__half2*>(&swh[SWZ128(row, c4)])     = wh0;
                *reinterpret_cast<__half2*>(&swh[SWZ128(row, c4) + 2]) = wh1;
                *reinterpret_cast<__half2*>(&swl[SWZ128(row, c4)])     = wl0;
                *reinterpret_cast<__half2*>(&swl[SWZ128(row, c4) + 2]) = wl1;
            }
            __syncthreads();

            #pragma unroll
            for (int ks = 0; ks < 4; ks++) {
                unsigned ah[2][4], al[2][4];
                #pragma unroll
                for (int mt = 0; mt < 2; mt++) {
                    int row = wm * 32 + mt * 16 + ((q4 & 1) << 3) + (lane & 7);
                    int ch  = 2 * ks + (q4 >> 1);
                    int so  = row * 64 + ((ch ^ (row & 7)) << 3);
                    ldsm4(ah[mt], &sxh[so]);
                    ldsm4(al[mt], &sxl[so]);
                }
                #pragma unroll
                for (int np = 0; np < 4; np++) {
                    unsigned bh[4], bl[4];
                    int row = ks * 16 + ((q4 & 1) << 3) + (lane & 7);
                    int ch  = wn * 8 + np * 2 + (q4 >> 1);
                    int so  = row * 128 + ((ch ^ (row & 7)) << 3);
                    ldsm4t(bh, &swh[so]);
                    ldsm4t(bl, &swl[so]);
                    #pragma unroll
                    for (int mt = 0; mt < 2; mt++) {
                        mma16(C[mt][2 * np],     ah[mt], bh[0], bh[1]);
                        mma16(C[mt][2 * np + 1], ah[mt], bh[2], bh[3]);
                        mma16(C[mt][2 * np],     al[mt], bh[0], bh[1]);
                        mma16(C[mt][2 * np + 1], al[mt], bh[2], bh[3]);
                        mma16(C[mt][2 * np],     ah[mt], bl[0], bl[1]);
                        mma16(C[mt][2 * np + 1], ah[mt], bl[2], bl[3]);
                    }
                }
            }
        }

        __half* dst = kvsel ? g_vh : g_kh;
        float* cache = cache_k + (size_t)kvsel * NMB * NW * NKVH * NHD;

        #pragma unroll
        for (int mt = 0; mt < 2; mt++) {
            #pragma unroll
            for (int rr = 0; rr < 2; rr++) {
                int row = m0 + wm * 32 + mt * 16 + rr * 8 + g;
                int b = row >> 11;
                int s = row & 2047;
                #pragma unroll
                for (int ns = 0; ns < 8; ns++) {
                    int coll = n0 + wn * 64 + ns * 8 + 2 * t4;
                    int head = coll >> 7;
                    int hd = coll & 127;
                    float v0 = C[mt][ns][2 * rr];
                    float v1 = C[mt][ns][2 * rr + 1];
                    if (!kvsel) {
                        float2 cs = *reinterpret_cast<const float2*>(
                            &freqs[(s * 64 + (hd >> 1)) * 2]);
                        float r0v = v0 * cs.x - v1 * cs.y;
                        float r1v = v0 * cs.y + v1 * cs.x;
                        v0 = r0v; v1 = r1v;
                    }
                    __half2 hv = __floats2half2_rn(v0, v1);
                    float2 cf = __half22float2(hv);
                    *reinterpret_cast<float2*>(
                        &cache[(((size_t)b * NW + s) * NKVH + head) * NHD + hd]) = cf;
                    *reinterpret_cast<__half2*>(
                        &dst[(((size_t)b * NKVH + head) * NS + s) * NHD + hd]) = hv;
                }
            }
        }
        return;
    }

    if (bid < PREP_PROJ_BLOCKS + PREP_QPROJ_BLOCKS) {
        // ---- Q projection role (plain fp16) ----
        int rb = bid - PREP_PROJ_BLOCKS;
        __half* sx = psm;
        __half* sw = psm + 16384;

        const int m0 = (rb >> 5) * 128;
        const int n0 = (rb & 31) * 128;

        #pragma unroll
        for (int i = 0; i < 16; i++) {
            int idx = tid + i * 256;
            int row = idx >> 5;
            int c4  = (idx & 31) * 4;
            float4 v = *reinterpret_cast<const float4*>(&x[(size_t)(m0 + row) * 128 + c4]);
            *reinterpret_cast<__half2*>(&sx[SWZ128(row, c4)])     = __floats2half2_rn(v.x, v.y);
            *reinterpret_cast<__half2*>(&sx[SWZ128(row, c4) + 2]) = __floats2half2_rn(v.z, v.w);

            float4 wv4 = *reinterpret_cast<const float4*>(&wq[(size_t)row * 4096 + n0 + c4]);
            *reinterpret_cast<__half2*>(&sw[SWZ128(row, c4)])     = __floats2half2_rn(wv4.x, wv4.y);
            *reinterpret_cast<__half2*>(&sw[SWZ128(row, c4) + 2]) = __floats2half2_rn(wv4.z, wv4.w);
        }
        __syncthreads();

        float C[2][8][4] = {};

        #pragma unroll
        for (int ks = 0; ks < 8; ks++) {
            unsigned a[2][4];
            #pragma unroll
            for (int mt = 0; mt < 2; mt++) {
                int row = wm * 32 + mt * 16 + ((q4 & 1) << 3) + (lane & 7);
                int ch  = 2 * ks + (q4 >> 1);
                ldsm4(a[mt], &sx[row * 128 + ((ch ^ (row & 7)) << 3)]);
            }
            #pragma unroll
            for (int np = 0; np < 4; np++) {
                unsigned bb[4];
                int row = ks * 16 + ((q4 & 1) << 3) + (lane & 7);
                int ch  = wn * 8 + np * 2 + (q4 >> 1);
                ldsm4t(bb, &sw[row * 128 + ((ch ^ (row & 7)) << 3)]);
                mma16(C[0][2 * np],     a[0], bb[0], bb[1]);
                mma16(C[0][2 * np + 1], a[0], bb[2], bb[3]);
                mma16(C[1][2 * np],     a[1], bb[0], bb[1]);
                mma16(C[1][2 * np + 1], a[1], bb[2], bb[3]);
            }
        }

        #pragma unroll
        for (int mt = 0; mt < 2; mt++) {
            #pragma unroll
            for (int rr = 0; rr < 2; rr++) {
                int row = m0 + wm * 32 + mt * 16 + rr * 8 + g;
                int b = row >> 11;
                int s = row & 2047;
                #pragma unroll
                for (int ns = 0; ns < 8; ns++) {
                    int col = n0 + wn * 64 + ns * 8 + 2 * t4;
                    int head = col >> 7;
                    int hd = col & 127;
                    float2 cs = *reinterpret_cast<const float2*>(
                        &freqs[(s * 64 + (hd >> 1)) * 2]);
                    float v0 = C[mt][ns][2 * rr];
                    float v1 = C[mt][ns][2 * rr + 1];
                    float r0v = (v0 * cs.x - v1 * cs.y) * KQSCALE;
                    float r1v = (v0 * cs.y + v1 * cs.x) * KQSCALE;
                    *reinterpret_cast<__half2*>(
                        &g_qh[(((size_t)b * NH + head) * NS + s) * NHD + hd]) =
                        __floats2half2_rn(r0v, r1v);
                }
            }
        }
        return;
    }

    // ---- convert role ----
    int rc = bid - PREP_PROJ_BLOCKS - PREP_QPROJ_BLOCKS;
    #pragma unroll
    for (int t = 0; t < 4; t++) {
        int i = rc * 256 + tid + t * 65536;
        float2 v = reinterpret_cast<const float2*>(wo)[i];
        reinterpret_cast<__half2*>(g_woh)[i] = __floats2half2_rn(v.x, v.y);
    }
}

// ---------------------------------------------------------------------------
// FA2-style fp16 flash attention, 2 CTAs/SM, stateless softmax, 1 barrier/tile.
// ---------------------------------------------------------------------------
#define QT 128
#define KT 64
#define SQ_H (QT * 128)
#define SK_H (KT * 128)
#define ATTN_SMEM_BYTES ((SQ_H + 4 * SK_H) * 2)   // 98304

__global__ void __launch_bounds__(256, 2) attn_kernel() {
    extern __shared__ __half smh[];
    __half* sq  = smh;
    __half* skb = sq + SQ_H;
    __half* svb = skb + 2 * SK_H;

    const int qb = (int)gridDim.x - 1 - (int)blockIdx.x;
    const int h  = blockIdx.y;
    const int b  = blockIdx.z;
    const int kvh = h >> 2;
    const int tid  = threadIdx.x;
    const int lane = tid & 31;
    const int w    = tid >> 5;
    const int g    = lane >> 2;
    const int t4   = lane & 3;
    const int q4   = lane >> 3;

    const __half* qg = g_qh + (((size_t)b * NH + h) * NS + (size_t)qb * QT) * NHD;
    const __half* kg = g_kh + ((size_t)b * NKVH + kvh) * NS * NHD;
    const __half* vg = g_vh + ((size_t)b * NKVH + kvh) * NS * NHD;

    const int nkb = 2 * qb + 2;

    #pragma unroll
    for (int i = 0; i < 4; i++) {
        int idx = tid + i * 256;
        int row = idx >> 4, c = idx & 15;
        cpasync16(&skb[SWZ128(row, c * 8)], &kg[(size_t)row * 128 + c * 8]);
        cpasync16(&svb[SWZ128(row, c * 8)], &vg[(size_t)row * 128 + c * 8]);
    }
    asm volatile("cp.async.commit_group;");

    #pragma unroll
    for (int i = 0; i < 8; i++) {
        int idx = tid + i * 256;
        int row = idx >> 4, c = idx & 15;
        *reinterpret_cast<uint4*>(&sq[SWZ128(row, c * 8)]) =
            *reinterpret_cast<const uint4*>(&qg[(size_t)row * 128 + c * 8]);
    }

    float O[16][4] = {};
    float Lc[4] = {};

    for (int kb = 0; kb < nkb; kb++) {
        const int cur = kb & 1;

        asm volatile("cp.async.wait_group 0;");
        __syncthreads();

        if (kb + 1 < nkb) {
            __half* skn = skb + (cur ^ 1) * SK_H;
            __half* svn = svb + (cur ^ 1) * SK_H;
            const size_t off = (size_t)(kb + 1) * KT * 128;
            #pragma unroll
            for (int i = 0; i < 4; i++) {
                int idx = tid + i * 256;
                int row = idx >> 4, c = idx & 15;
                cpasync16(&skn[SWZ128(row, c * 8)], &kg[off + (size_t)row * 128 + c * 8]);
                cpasync16(&svn[SWZ128(row, c * 8)], &vg[off + (size_t)row * 128 + c * 8]);
            }
            asm volatile("cp.async.commit_group;");
        }

        const __half* skc = skb + cur * SK_H;
        const __half* svc = svb + cur * SK_H;

        const bool skip = (kb * KT > qb * QT + w * 16 + 15);
        if (!skip) {
            // ---- scores: C = Q . K^T, warp tile 16x64 ----
            float C[8][4] = {};
            #pragma unroll
            for (int ks = 0; ks < 8; ks++) {
                unsigned qa[4];
                {
                    int row = w * 16 + ((q4 & 1) << 3) + (lane & 7);
                    int ch  = 2 * ks + (q4 >> 1);
                    ldsm4(qa, &sq[row * 128 + ((ch ^ (row & 7)) << 3)]);
                }
                #pragma unroll
                for (int np = 0; np < 4; np++) {
                    unsigned bb[4];
                    int n  = np * 16 + ((q4 >> 1) << 3) + (lane & 7);
                    int ch = 2 * ks + (q4 & 1);
                    ldsm4(bb, &skc[n * 128 + ((ch ^ (n & 7)) << 3)]);
                    mma16(C[2 * np],     qa, bb[0], bb[1]);
                    mma16(C[2 * np + 1], qa, bb[2], bb[3]);
                }
            }

            // causal mask (log2 domain; -30 -> exp2 = 0 in fp16)
            if (kb * KT + KT - 1 > qb * QT + w * 16) {
                const int grow0 = qb * QT + w * 16 + g;
                #pragma unroll
                for (int ns = 0; ns < 8; ns++) {
                    int gc = kb * KT + ns * 8 + 2 * t4;
                    if (gc     > grow0)     C[ns][0] = -30.f;
                    if (gc + 1 > grow0)     C[ns][1] = -30.f;
                    if (gc     > grow0 + 8) C[ns][2] = -30.f;
                    if (gc + 1 > grow0 + 8) C[ns][3] = -30.f;
                }
            }

            // ---- stateless softmax: P = exp2(C), packed to fp16 A-frags ----
            unsigned pa[4][4];
            #pragma unroll
            for (int j = 0; j < 4; j++) {
                pa[j][0] = ex2pack(C[2 * j][0],     C[2 * j][1]);
                pa[j][1] = ex2pack(C[2 * j][2],     C[2 * j][3]);
                pa[j][2] = ex2pack(C[2 * j + 1][0], C[2 * j + 1][1]);
                pa[j][3] = ex2pack(C[2 * j + 1][2], C[2 * j + 1][3]);
            }

            // normalizer: Lc += P @ ones
            #pragma unroll
            for (int j = 0; j < 4; j++)
                mma16(Lc, pa[j], ONES_H2, ONES_H2);

            // ---- PV: O += P . V, warp tile 16x128 ----
            #pragma unroll
            for (int j = 0; j < 4; j++) {
                #pragma unroll
                for (int ng = 0; ng < 8; ng++) {
                    unsigned bb[4];
                    int row = j * 16 + ((q4 & 1) << 3) + (lane & 7);
                    int ch  = ng * 2 + (q4 >> 1);
                    ldsm4t(bb, &svc[row * 128 + ((ch ^ (row & 7)) << 3)]);
                    mma16(O[2 * ng],     pa[j], bb[0], bb[1]);
                    mma16(O[2 * ng + 1], pa[j], bb[2], bb[3]);
                }
            }
        }
    }

    {
        float inv0 = 1.f / Lc[0];
        float inv1 = 1.f / Lc[2];
        int s0r = qb * QT + w * 16 + g;
        int s1r = s0r + 8;
        size_t base0 = ((size_t)b * NS + s0r) * (NH * NHD) + (size_t)h * NHD;
        size_t base1 = ((size_t)b * NS + s1r) * (NH * NHD) + (size_t)h * NHD;
        #pragma unroll
        for (int ns = 0; ns < 16; ns++) {
            int col = ns * 8 + 2 * t4;
            *reinterpret_cast<__half2*>(&g_attnh[base0 + col]) =
                __floats2half2_rn(O[ns][0] * inv0, O[ns][1] * inv0);
            *reinterpret_cast<__half2*>(&g_attnh[base1 + col]) =
                __floats2half2_rn(O[ns][2] * inv1, O[ns][3] * inv1);
        }
    }
}

// ---------------------------------------------------------------------------
// Output projection, stage 1 (split-K 8-way) + cache zero-fill role.
// ---------------------------------------------------------------------------
#define OSA_H (32 * 64)
#define OSW_H (64 * 128)
#define OPROJ_SMEM_BYTES ((2 * OSA_H + 2 * OSW_H) * 2)   // 40960
#define OPROJ_GEMM_BLOCKS 1024
#define OPROJ_ZERO_BLOCKS 768
#define OPROJ_BLOCKS (OPROJ_GEMM_BLOCKS + OPROJ_ZERO_BLOCKS)

__global__ void __launch_bounds__(256) oproj_split_kernel(float* __restrict__ cache_k) {
    const int bid = blockIdx.x;
    const int tid = threadIdx.x;

    if (bid >= OPROJ_GEMM_BLOCKS) {
        int rb = bid - OPROJ_GEMM_BLOCKS;
        const size_t nz = 3145728, per = 4194304;
        float4 z = make_float4(0.f, 0.f, 0.f, 0.f);
        #pragma unroll 4
        for (int t = tid; t < 8192; t += 256) {
            size_t i = (size_t)rb * 8192 + t;
            size_t c = i / nz, j = i - c * nz;
            size_t off;
            if (j < 524288)        off = 524288 + j;
            else if (j < 1048576)  off = 1572864 + (j - 524288);
            else                   off = 2097152 + (j - 1048576);
            reinterpret_cast<float4*>(cache_k)[c * per + off] = z;
        }
        return;
    }

    extern __shared__ __half osm[];
    __half* sa = osm;
    __half* sw = osm + 2 * OSA_H;

    const int ks4 = bid >> 7;              // 0..7
    const int m0  = (bid & 127) * 32;
    const int kbase = ks4 * 512;
    const int lane = tid & 31;
    const int w    = tid >> 5;
    const int wm   = w >> 2;
    const int wn   = w & 3;
    const int g    = lane >> 2;
    const int t4   = lane & 3;
    const int q4   = lane >> 3;

    float C[4][4] = {};

    {
        int idx = tid;
        int row = idx >> 3, c = idx & 7;
        cpasync16(&sa[SWZ64(row, c * 8)],
                  &g_attnh[(size_t)(m0 + row) * 4096 + kbase + c * 8]);
    }
    #pragma unroll
    for (int i = 0; i < 4; i++) {
        int idx = tid + i * 256;
        int row = idx >> 4, c = idx & 15;
        cpasync16(&sw[SWZ128(row, c * 8)], &g_woh[(size_t)(kbase + row) * 128 + c * 8]);
    }
    asm volatile("cp.async.commit_group;");

    for (int kc = 0; kc < 8; kc++) {
        const int cur = kc & 1;
        if (kc + 1 < 8) {
            __half* san = sa + (cur ^ 1) * OSA_H;
            __half* swn = sw + (cur ^ 1) * OSW_H;
            const int k0 = kbase + (kc + 1) * 64;
            {
                int idx = tid;
                int row = idx >> 3, c = idx & 7;
                cpasync16(&san[SWZ64(row, c * 8)],
                          &g_attnh[(size_t)(m0 + row) * 4096 + k0 + c * 8]);
            }
            #pragma unroll
            for (int i = 0; i < 4; i++) {
                int idx = tid + i * 256;
                int row = idx >> 4, c = idx & 15;
                cpasync16(&swn[SWZ128(row, c * 8)],
                          &g_woh[(size_t)(k0 + row) * 128 + c * 8]);
            }
            asm volatile("cp.async.commit_group;");
            asm volatile("cp.async.wait_group 1;");
        } else {
            asm volatile("cp.async.wait_group 0;");
        }
        __syncthreads();

        const __half* sac = sa + cur * OSA_H;
        const __half* swc = sw + cur * OSW_H;

        #pragma unroll
        for (int ks = 0; ks < 4; ks++) {
            unsigned a[4];
            {
                int row = wm * 16 + ((q4 & 1) << 3) + (lane & 7);
                int ch  = 2 * ks + (q4 >> 1);
                ldsm4(a, &sac[row * 64 + ((ch ^ (row & 7)) << 3)]);
            }
            #pragma unroll
            for (int np = 0; np < 2; np++) {
                unsigned bb[4];
                int row = ks * 16 + ((q4 & 1) << 3) + (lane & 7);
                int ch  = wn * 4 + np * 2 + (q4 >> 1);
                ldsm4t(bb, &swc[row * 128 + ((ch ^ (row & 7)) << 3)]);
                mma16(C[2 * np],     a, bb[0], bb[1]);
                mma16(C[2 * np + 1], a, bb[2], bb[3]);
            }
        }
        __syncthreads();
    }

    {
        float* part = g_opart + (size_t)ks4 * 4096 * 128;
        int r0 = m0 + wm * 16 + g;
        #pragma unroll
        for (int ns = 0; ns < 4; ns++) {
            int col = wn * 32 + ns * 8 + 2 * t4;
            *reinterpret_cast<float2*>(&part[(size_t)r0 * 128 + col]) =
                make_float2(C[ns][0], C[ns][1]);
            *reinterpret_cast<float2*>(&part[(size_t)(r0 + 8) * 128 + col]) =
                make_float2(C[ns][2], C[ns][3]);
        }
    }
}

// ---------------------------------------------------------------------------
// Output projection, stage 2: out = sum of 8 partials.
// ---------------------------------------------------------------------------
__global__ void __launch_bounds__(256) oproj_reduce_kernel(float* __restrict__ out) {
    const int i = blockIdx.x * 256 + threadIdx.x;   // 0..131071 float4
    const float4* p = reinterpret_cast<const float4*>(g_opart);
    float4 r = make_float4(0.f, 0.f, 0.f, 0.f);
    #pragma unroll
    for (int k = 0; k < 8; k++) {
        float4 a = p[i + (size_t)k * 131072];
        r.x += a.x; r.y += a.y; r.z += a.z; r.w += a.w;
    }
    reinterpret_cast<float4*>(out)[i] = r;
}

// ---------------------------------------------------------------------------
// Launch
// ---------------------------------------------------------------------------
extern "C" void kernel_launch(void* const* d_in, const int* in_sizes, int n_in,
                              void* d_out, int out_size) {
    const float* x     = (const float*)d_in[0];
    const float* wq    = (const float*)d_in[1];
    const float* wk    = (const float*)d_in[2];
    const float* wv    = (const float*)d_in[3];
    const float* wo    = (const float*)d_in[4];
    const float* freqs = (const float*)d_in[5];

    float* out = (float*)d_out;
    float* cache_k_out = out + (size_t)NB * NS * ND;

    (void)in_sizes; (void)n_in; (void)out_size;

    static int attrs_set = 0;
    if (!attrs_set) {
        cudaFuncSetAttribute(attn_kernel, cudaFuncAttributeMaxDynamicSharedMemorySize,
                             ATTN_SMEM_BYTES);
        cudaFuncSetAttribute(oproj_split_kernel, cudaFuncAttributeMaxDynamicSharedMemorySize,
                             OPROJ_SMEM_BYTES);
        cudaFuncSetAttribute(prep_kernel, cudaFuncAttributeMaxDynamicSharedMemorySize,
                             PREP_SMEM_BYTES);
        attrs_set = 1;
    }

    prep_kernel<<<PREP_BLOCKS, 256, PREP_SMEM_BYTES>>>(x, wq, wk, wv, freqs, wo,
                                                       cache_k_out);

    attn_kernel<<<dim3(NS / QT, NH, NB), 256, ATTN_SMEM_BYTES>>>();

    oproj_split_kernel<<<OPROJ_BLOCKS, 256, OPROJ_SMEM_BYTES>>>(cache_k_out);
    oproj_reduce_kernel<<<512, 256>>>(out);
}